// round 8
// baseline (speedup 1.0000x reference)
#include <cuda_runtime.h>
#include <cuda_bf16.h>
#include <cstdint>

// Problem: y[b,e] = relu(sum_a action[b,a] * conv_w[e,a] + conv_b[e])
// out[b,e,h,w] = y[b,e] broadcast over 64x64 spatial.
// B=128, A=256, E=256, H=W=64. Output fp32, 512 MB -> pure HBM-write-bound.
//
// A/B vs R6 champion (STG.256, 73.9us, 83.0% DRAM): stores now go through
// the TMA bulk-copy path. Each block fills a 16 KB smem plane buffer, then
// one thread issues a single cp.async.bulk.global.shared::cta of the whole
// plane. Tests whether DRAM write-burst shaping (not SM store issue) is the
// remaining 17% gap.

#define B_DIM   128
#define A_DIM   256
#define E_DIM   256
#define HW      4096                 // 64*64
#define NPLANES (B_DIM * E_DIM)      // 32768
#define PLANE_BYTES (HW * 4)         // 16384

__global__ __launch_bounds__(256)
void fused_embed_fill_kernel(const float*  __restrict__ action,
                             const float*  __restrict__ conv_w,
                             const float*  __restrict__ conv_b,
                             float*        __restrict__ out)
{
    __shared__ __align__(128) float4 s_buf[HW / 4];   // 16 KB

    const int plane = blockIdx.x;          // b*256 + e
    const int b = plane >> 8;
    const int e = plane & 255;
    const int t    = threadIdx.x;
    const int lane = t & 31;

    // --- per-warp redundant dot product over A=256 -------------------------
    const float4* a4 = reinterpret_cast<const float4*>(action + b * A_DIM);
    const float4* w4 = reinterpret_cast<const float4*>(conv_w + e * A_DIM);

    float4 av0 = a4[lane];
    float4 av1 = a4[lane + 32];
    float4 wv0 = w4[lane];
    float4 wv1 = w4[lane + 32];

    float s;
    s = av0.x * wv0.x;
    s = fmaf(av0.y, wv0.y, s);
    s = fmaf(av0.z, wv0.z, s);
    s = fmaf(av0.w, wv0.w, s);
    s = fmaf(av1.x, wv1.x, s);
    s = fmaf(av1.y, wv1.y, s);
    s = fmaf(av1.z, wv1.z, s);
    s = fmaf(av1.w, wv1.w, s);

    s += __shfl_xor_sync(0xFFFFFFFF, s, 16);
    s += __shfl_xor_sync(0xFFFFFFFF, s, 8);
    s += __shfl_xor_sync(0xFFFFFFFF, s, 4);
    s += __shfl_xor_sync(0xFFFFFFFF, s, 2);
    s += __shfl_xor_sync(0xFFFFFFFF, s, 1);

    const float v = fmaxf(s + __ldg(conv_b + e), 0.0f);
    const float4 v4 = make_float4(v, v, v, v);

    // --- stage plane in smem ------------------------------------------------
    s_buf[t]       = v4;
    s_buf[t + 256] = v4;
    s_buf[t + 512] = v4;
    s_buf[t + 768] = v4;
    __syncthreads();

    // --- single 16 KB TMA bulk store ---------------------------------------
    asm volatile("fence.proxy.async.shared::cta;" ::: "memory");
    if (t == 0) {
        uint32_t saddr;
        asm("{ .reg .u64 tmp; cvta.to.shared.u64 tmp, %1; cvt.u32.u64 %0, tmp; }"
            : "=r"(saddr) : "l"(s_buf));
        float* dst = out + (size_t)plane * HW;
        asm volatile(
            "cp.async.bulk.global.shared::cta.bulk_group [%0], [%1], %2;"
            :: "l"(dst), "r"(saddr), "n"(PLANE_BYTES) : "memory");
        asm volatile("cp.async.bulk.commit_group;" ::: "memory");
        asm volatile("cp.async.bulk.wait_group 0;" ::: "memory");
    }
    // keep smem alive until the bulk copy's reads are complete (t0 waited)
    __syncthreads();
}

extern "C" void kernel_launch(void* const* d_in, const int* in_sizes, int n_in,
                              void* d_out, int out_size)
{
    const float* action = (const float*)d_in[0];   // [128, 256]
    const float* conv_w = (const float*)d_in[1];   // [256, 256]
    const float* conv_b = (const float*)d_in[2];   // [256]
    float* out = (float*)d_out;                    // [128, 256, 64, 64] fp32

    fused_embed_fill_kernel<<<NPLANES, 256>>>(action, conv_w, conv_b, out);
}

// round 9
// speedup vs baseline: 1.0038x; 1.0038x over previous
#include <cuda_runtime.h>
#include <cuda_bf16.h>
#include <cstdint>

// Problem: y[b,e] = relu(sum_a action[b,a] * conv_w[e,a] + conv_b[e])
// out[b,e,h,w] = y[b,e] broadcast over 64x64 spatial.
// B=128, A=256, E=256, H=W=64. Output fp32, 512 MB -> pure HBM-write-bound.
// Measured ceiling across {STG.128, STG.256, TMA bulk} x {wb, cs, wt} x 4
// grid shapes: ~6.5-6.6 TB/s (81-83% of spec). This round: tail-trim only.
//
// 512-thread blocks, 2 planes per block (same b). Warps 0-7 compute plane 0's
// dot (per-warp redundant), warps 8-15 plane 1's. Each thread issues exactly
// ONE 256-bit store (32 B): 512 threads x 32 B = 16 KB = one plane per
// half-block. Write-back policy (best of the hint sweep).

#define B_DIM   128
#define A_DIM   256
#define E_DIM   256
#define HW      4096                 // 64*64
#define NPLANES (B_DIM * E_DIM)      // 32768
#define NBLOCKS (NPLANES / 2)        // 16384

__device__ __forceinline__ void stg256(float* p, float v)
{
    asm volatile(
        "st.global.v8.f32 [%0], {%1,%1,%1,%1,%1,%1,%1,%1};"
        :: "l"(p), "f"(v) : "memory");
}

__global__ __launch_bounds__(512)
void fused_embed_fill_kernel(const float*  __restrict__ action,
                             const float*  __restrict__ conv_w,
                             const float*  __restrict__ conv_b,
                             float*        __restrict__ out)
{
    const int base_plane = blockIdx.x * 2;       // 2 consecutive planes, same b
    const int b    = base_plane >> 8;
    const int t    = threadIdx.x;                // 0..511
    const int half = t >> 8;                     // 0 or 1 -> which plane
    const int ht   = t & 255;                    // thread index within half
    const int lane = t & 31;

    const int plane = base_plane + half;
    const int e = plane & 255;

    // --- per-warp redundant dot product over A=256 -------------------------
    const float4* a4 = reinterpret_cast<const float4*>(action + b * A_DIM);
    const float4* w4 = reinterpret_cast<const float4*>(conv_w + e * A_DIM);

    float4 av0 = a4[lane];
    float4 av1 = a4[lane + 32];
    float4 wv0 = w4[lane];
    float4 wv1 = w4[lane + 32];

    float s;
    s = av0.x * wv0.x;
    s = fmaf(av0.y, wv0.y, s);
    s = fmaf(av0.z, wv0.z, s);
    s = fmaf(av0.w, wv0.w, s);
    s = fmaf(av1.x, wv1.x, s);
    s = fmaf(av1.y, wv1.y, s);
    s = fmaf(av1.z, wv1.z, s);
    s = fmaf(av1.w, wv1.w, s);

    s += __shfl_xor_sync(0xFFFFFFFF, s, 16);
    s += __shfl_xor_sync(0xFFFFFFFF, s, 8);
    s += __shfl_xor_sync(0xFFFFFFFF, s, 4);
    s += __shfl_xor_sync(0xFFFFFFFF, s, 2);
    s += __shfl_xor_sync(0xFFFFFFFF, s, 1);

    const float v = fmaxf(s + __ldg(conv_b + e), 0.0f);

    // --- one 256-bit store per thread: 256 threads x 32 B = 8 KB ... x2 ----
    // Each half-block owns its plane; thread ht writes chunk ht and ht+256?
    // No: 256 threads * 32 B = 8 KB, plane is 16 KB -> each thread writes 2
    // chunks? Plane = 4096 floats = 512 chunks of 8 floats. Half-block has
    // 256 threads -> 2 chunks each. Keep both stores independent.
    float* p = out + (size_t)plane * HW + ht * 8;

    stg256(p,           v);
    stg256(p + 2048,    v);    // second half of the plane (256*8 floats on)
}

extern "C" void kernel_launch(void* const* d_in, const int* in_sizes, int n_in,
                              void* d_out, int out_size)
{
    const float* action = (const float*)d_in[0];   // [128, 256]
    const float* conv_w = (const float*)d_in[1];   // [256, 256]
    const float* conv_b = (const float*)d_in[2];   // [256]
    float* out = (float*)d_out;                    // [128, 256, 64, 64] fp32

    fused_embed_fill_kernel<<<NBLOCKS, 512>>>(action, conv_w, conv_b, out);
}

// round 10
// speedup vs baseline: 1.0073x; 1.0034x over previous
#include <cuda_runtime.h>
#include <cuda_bf16.h>
#include <cstdint>

// Problem: y[b,e] = relu(sum_a action[b,a] * conv_w[e,a] + conv_b[e])
// out[b,e,h,w] = y[b,e] broadcast over 64x64 spatial.
// B=128, A=256, E=256, H=W=64. Output fp32, 512 MB -> pure HBM-write-bound.
//
// FINAL (Round-6 champion, 73.9us, 83.0% DRAM / 6575 GB/s). Exhaustive sweep
// over store width {128b, 256b, TMA bulk}, cache policy {wb, cs, wt}, and
// grid/block shape {32768x256, 16384x512, 8192x256-PPB4, persistent} all
// plateau at 81-83% DRAM: ~6.5-6.6 TB/s is this part's pure-write HBM
// ceiling. This kernel sits at it.
//
// Shape: one block per (b,e) plane. All 8 warps redundantly compute the
// A=256 dot product (inputs fully L2-resident, 384 KB total), shuffle-
// reduce, then each thread issues 2x 256-bit write-back stores (32 B each):
// 256 threads x 64 B = 16 KB plane, perfectly coalesced.

#define B_DIM   128
#define A_DIM   256
#define E_DIM   256
#define HW      4096                 // 64*64
#define NPLANES (B_DIM * E_DIM)      // 32768

__device__ __forceinline__ void stg256(float* p, float v)
{
    asm volatile(
        "st.global.v8.f32 [%0], {%1,%1,%1,%1,%1,%1,%1,%1};"
        :: "l"(p), "f"(v) : "memory");
}

__global__ __launch_bounds__(256)
void fused_embed_fill_kernel(const float*  __restrict__ action,
                             const float*  __restrict__ conv_w,
                             const float*  __restrict__ conv_b,
                             float*        __restrict__ out)
{
    const int plane = blockIdx.x;          // b*256 + e
    const int b = plane >> 8;
    const int e = plane & 255;
    const int t    = threadIdx.x;
    const int lane = t & 31;

    // --- per-warp redundant dot product over A=256 -------------------------
    const float4* a4 = reinterpret_cast<const float4*>(action + b * A_DIM);
    const float4* w4 = reinterpret_cast<const float4*>(conv_w + e * A_DIM);

    float4 av0 = a4[lane];
    float4 av1 = a4[lane + 32];
    float4 wv0 = w4[lane];
    float4 wv1 = w4[lane + 32];

    float s;
    s = av0.x * wv0.x;
    s = fmaf(av0.y, wv0.y, s);
    s = fmaf(av0.z, wv0.z, s);
    s = fmaf(av0.w, wv0.w, s);
    s = fmaf(av1.x, wv1.x, s);
    s = fmaf(av1.y, wv1.y, s);
    s = fmaf(av1.z, wv1.z, s);
    s = fmaf(av1.w, wv1.w, s);

    s += __shfl_xor_sync(0xFFFFFFFF, s, 16);
    s += __shfl_xor_sync(0xFFFFFFFF, s, 8);
    s += __shfl_xor_sync(0xFFFFFFFF, s, 4);
    s += __shfl_xor_sync(0xFFFFFFFF, s, 2);
    s += __shfl_xor_sync(0xFFFFFFFF, s, 1);

    const float v = fmaxf(s + __ldg(conv_b + e), 0.0f);

    // --- fill this plane: 4096 floats = 512 x 32B chunks --------------------
    // Thread t writes chunks t and t+256 (each 8 floats, 32B-aligned).
    float* p = out + (size_t)plane * HW + t * 8;

    stg256(p,            v);
    stg256(p + 256 * 8,  v);
}

extern "C" void kernel_launch(void* const* d_in, const int* in_sizes, int n_in,
                              void* d_out, int out_size)
{
    const float* action = (const float*)d_in[0];   // [128, 256]
    const float* conv_w = (const float*)d_in[1];   // [256, 256]
    const float* conv_b = (const float*)d_in[2];   // [256]
    float* out = (float*)d_out;                    // [128, 256, 64, 64] fp32

    fused_embed_fill_kernel<<<NPLANES, 256>>>(action, conv_w, conv_b, out);
}

// round 11
// speedup vs baseline: 1.0103x; 1.0030x over previous
#include <cuda_runtime.h>
#include <cuda_bf16.h>
#include <cstdint>

// Problem: y[b,e] = relu(sum_a action[b,a] * conv_w[e,a] + conv_b[e])
// out[b,e,h,w] = y[b,e] broadcast over 64x64 spatial.
// B=128, A=256, E=256, H=W=64. Output fp32, 512 MB -> pure HBM-write-bound.
//
// FINAL kernel (Round-6 champion; best measured 73.9us total, 72.5us kernel,
// 83.0% DRAM / 6575 GB/s). Nine-configuration sweep over store width
// {STG.128, STG.256, TMA bulk} x cache policy {wb, cs, wt} x block/grid
// shape {32768x256, 16384x512, 8192x256-PPB4, persistent 1184, split
// GEMM+fill} all plateau at 81-83% DRAM: ~6.5-6.6 TB/s is this GB300's
// pure-write HBM ceiling. This kernel sits at it; SM issue (22%), L2 (62%),
// and occupancy (85%) are all non-binding.
//
// Shape: one block per (b,e) plane. All 8 warps redundantly compute the
// A=256 dot product (inputs fully L2-resident, 384 KB total), shuffle-
// reduce, then each thread issues 2x 256-bit write-back stores (32 B each):
// 256 threads x 64 B = 16 KB plane, perfectly coalesced.

#define B_DIM   128
#define A_DIM   256
#define E_DIM   256
#define HW      4096                 // 64*64
#define NPLANES (B_DIM * E_DIM)      // 32768

__device__ __forceinline__ void stg256(float* p, float v)
{
    asm volatile(
        "st.global.v8.f32 [%0], {%1,%1,%1,%1,%1,%1,%1,%1};"
        :: "l"(p), "f"(v) : "memory");
}

__global__ __launch_bounds__(256)
void fused_embed_fill_kernel(const float*  __restrict__ action,
                             const float*  __restrict__ conv_w,
                             const float*  __restrict__ conv_b,
                             float*        __restrict__ out)
{
    const int plane = blockIdx.x;          // b*256 + e
    const int b = plane >> 8;
    const int e = plane & 255;
    const int t    = threadIdx.x;
    const int lane = t & 31;

    // --- per-warp redundant dot product over A=256 -------------------------
    const float4* a4 = reinterpret_cast<const float4*>(action + b * A_DIM);
    const float4* w4 = reinterpret_cast<const float4*>(conv_w + e * A_DIM);

    float4 av0 = a4[lane];
    float4 av1 = a4[lane + 32];
    float4 wv0 = w4[lane];
    float4 wv1 = w4[lane + 32];

    float s;
    s = av0.x * wv0.x;
    s = fmaf(av0.y, wv0.y, s);
    s = fmaf(av0.z, wv0.z, s);
    s = fmaf(av0.w, wv0.w, s);
    s = fmaf(av1.x, wv1.x, s);
    s = fmaf(av1.y, wv1.y, s);
    s = fmaf(av1.z, wv1.z, s);
    s = fmaf(av1.w, wv1.w, s);

    s += __shfl_xor_sync(0xFFFFFFFF, s, 16);
    s += __shfl_xor_sync(0xFFFFFFFF, s, 8);
    s += __shfl_xor_sync(0xFFFFFFFF, s, 4);
    s += __shfl_xor_sync(0xFFFFFFFF, s, 2);
    s += __shfl_xor_sync(0xFFFFFFFF, s, 1);

    const float v = fmaxf(s + __ldg(conv_b + e), 0.0f);

    // --- fill this plane: 4096 floats = 512 x 32B chunks --------------------
    // Thread t writes chunks t and t+256 (each 8 floats, 32B-aligned).
    float* p = out + (size_t)plane * HW + t * 8;

    stg256(p,            v);
    stg256(p + 256 * 8,  v);
}

extern "C" void kernel_launch(void* const* d_in, const int* in_sizes, int n_in,
                              void* d_out, int out_size)
{
    const float* action = (const float*)d_in[0];   // [128, 256]
    const float* conv_w = (const float*)d_in[1];   // [256, 256]
    const float* conv_b = (const float*)d_in[2];   // [256]
    float* out = (float*)d_out;                    // [128, 256, 64, 64] fp32

    fused_embed_fill_kernel<<<NPLANES, 256>>>(action, conv_w, conv_b, out);
}